// round 5
// baseline (speedup 1.0000x reference)
#include <cuda_runtime.h>
#include <cuda_bf16.h>
#include <cstdint>

#define NMAX 1000000
#define NBUCKETS 4096              // top 12 bits of the 47-bit key (bits 35..46)
#define CAP 768                    // max bucket size handled (mean ~244, 17+ sigma)
#define RB_THREADS 256

// ---------------------------------------------------------------------------
// Static device scratch (no allocations allowed anywhere)
// ---------------------------------------------------------------------------
__device__ uint64_t g_keys[NMAX];        // decode output (unordered)
__device__ uint64_t g_bkeys[NMAX];       // bucket-distributed keys (+first bit)
__device__ uint32_t g_bvals[NMAX];       // bucket-distributed original indices
__device__ int      g_newc[(size_t)NMAX * 4];
__device__ uint32_t g_hist[NBUCKETS];    // zero-init; reset by scan each call
__device__ uint32_t g_off[NBUCKETS + 1];
__device__ uint32_t g_cursor[NBUCKETS];
__device__ uint32_t g_uniq[NBUCKETS];
__device__ uint32_t g_ubase[NBUCKETS];

#define KEYMASK ((1ull << 47) - 1ull)
#define FIRSTBIT (1ull << 63)

// ---------------------------------------------------------------------------
// Packed f32x2 helpers (FFMA2 — PTX-only on sm_103a)
// ---------------------------------------------------------------------------
__device__ __forceinline__ void fma2(uint64_t& d, uint64_t a, uint64_t b, uint64_t c) {
    asm("fma.rn.f32x2 %0, %1, %2, %3;" : "=l"(d) : "l"(a), "l"(b), "l"(c));
}
__device__ __forceinline__ uint64_t dup2(float x) {
    uint64_t r; uint32_t u = __float_as_uint(x);
    asm("mov.b64 %0, {%1, %1};" : "=l"(r) : "r"(u));
    return r;
}
__device__ __forceinline__ uint64_t pack2(float lo, float hi) {
    uint64_t r;
    asm("mov.b64 %0, {%1, %2};" : "=l"(r) : "r"(__float_as_uint(lo)), "r"(__float_as_uint(hi)));
    return r;
}
__device__ __forceinline__ void unpack2(uint64_t v, float& lo, float& hi) {
    uint32_t a, b;
    asm("mov.b64 {%0, %1}, %2;" : "=r"(a), "=r"(b) : "l"(v));
    lo = __uint_as_float(a); hi = __uint_as_float(b);
}

// ---------------------------------------------------------------------------
// Kernel 1: MLP decode (f32x2) + key build + bucket histogram + zero tail
// ---------------------------------------------------------------------------
__global__ void __launch_bounds__(256)
decode_kernel(const float* __restrict__ feats,
              const int*   __restrict__ coords,
              const int*   __restrict__ mask,
              const float* __restrict__ W1, const float* __restrict__ b1,
              const float* __restrict__ W2, const float* __restrict__ b2,
              const float* __restrict__ W3, const float* __restrict__ b3,
              float* __restrict__ out, int n)
{
    __shared__ __align__(16) float sW1[64 * 32];
    __shared__ __align__(16) float sW2[32 * 16];
    __shared__ __align__(16) float sW3[16 * 3];
    __shared__ __align__(16) float sb1[32];
    __shared__ __align__(16) float sb2[16];
    __shared__ __align__(16) float sb3[4];

    for (int t = threadIdx.x; t < 64 * 32; t += blockDim.x) sW1[t] = W1[t];
    for (int t = threadIdx.x; t < 32 * 16; t += blockDim.x) sW2[t] = W2[t];
    for (int t = threadIdx.x; t < 16 * 3;  t += blockDim.x) sW3[t] = W3[t];
    if (threadIdx.x < 32) sb1[threadIdx.x] = b1[threadIdx.x];
    if (threadIdx.x < 16) sb2[threadIdx.x] = b2[threadIdx.x];
    if (threadIdx.x < 3)  sb3[threadIdx.x] = b3[threadIdx.x];
    __syncthreads();

    int i = blockIdx.x * blockDim.x + threadIdx.x;
    if (i >= n) return;

    // ---- layer 1: 64 -> 32 (packed pairs over output channels) ----
    uint64_t acc[16];
    const uint64_t* w1p = reinterpret_cast<const uint64_t*>(sW1);
#pragma unroll
    for (int p = 0; p < 16; p++) acc[p] = pack2(sb1[2 * p], sb1[2 * p + 1]);

    const float4* f4 = reinterpret_cast<const float4*>(feats) + (size_t)i * 16;
#pragma unroll
    for (int k4 = 0; k4 < 16; k4++) {
        float4 f = f4[k4];
        uint64_t a0 = dup2(f.x), a1 = dup2(f.y), a2 = dup2(f.z), a3 = dup2(f.w);
        const uint64_t* w0 = &w1p[(k4 * 4 + 0) * 16];
        const uint64_t* w1 = &w1p[(k4 * 4 + 1) * 16];
        const uint64_t* w2 = &w1p[(k4 * 4 + 2) * 16];
        const uint64_t* w3 = &w1p[(k4 * 4 + 3) * 16];
#pragma unroll
        for (int p = 0; p < 16; p++) {
            fma2(acc[p], a0, w0[p], acc[p]);
            fma2(acc[p], a1, w1[p], acc[p]);
            fma2(acc[p], a2, w2[p], acc[p]);
            fma2(acc[p], a3, w3[p], acc[p]);
        }
    }

    float h1[32];
#pragma unroll
    for (int p = 0; p < 16; p++) {
        float lo, hi;
        unpack2(acc[p], lo, hi);
        h1[2 * p]     = fmaxf(lo, 0.0f);
        h1[2 * p + 1] = fmaxf(hi, 0.0f);
    }

    // ---- layer 2: 32 -> 16 (packed) ----
    uint64_t acc2[8];
    const uint64_t* w2p = reinterpret_cast<const uint64_t*>(sW2);
#pragma unroll
    for (int p = 0; p < 8; p++) acc2[p] = pack2(sb2[2 * p], sb2[2 * p + 1]);
#pragma unroll
    for (int k = 0; k < 32; k++) {
        uint64_t a = dup2(h1[k]);
        const uint64_t* wr = &w2p[k * 8];
#pragma unroll
        for (int p = 0; p < 8; p++) fma2(acc2[p], a, wr[p], acc2[p]);
    }

    float h2[16];
#pragma unroll
    for (int p = 0; p < 8; p++) {
        float lo, hi;
        unpack2(acc2[p], lo, hi);
        h2[2 * p]     = fmaxf(lo, 0.0f);
        h2[2 * p + 1] = fmaxf(hi, 0.0f);
    }

    // ---- layer 3: 16 -> 3 (scalar) ----
    float o0 = sb3[0], o1 = sb3[1], o2 = sb3[2];
#pragma unroll
    for (int k = 0; k < 16; k++) {
        float a = h2[k];
        o0 = fmaf(a, sW3[k * 3 + 0], o0);
        o1 = fmaf(a, sW3[k * 3 + 1], o1);
        o2 = fmaf(a, sW3[k * 3 + 2], o2);
    }

    float m = (mask[i] != 0) ? 1.0f : 0.0f;
    o0 *= m; o1 *= m; o2 *= m;

    out[(size_t)3 * i + 0] = o0;
    out[(size_t)3 * i + 1] = o1;
    out[(size_t)3 * i + 2] = o2;

    // new_coords = coords with cols 1:4 += round(offsets)  (round-half-even)
    int4 c = reinterpret_cast<const int4*>(coords)[i];
    int n1 = c.y + (int)rintf(o0);
    int n2 = c.z + (int)rintf(o1);
    int n3 = c.w + (int)rintf(o2);

    reinterpret_cast<int4*>(g_newc)[i] = make_int4(c.x, n1, n2, n3);

    // 47-bit lexicographic key: c.x (11b) | 3 x 12-bit biased fields
    uint64_t key = ((uint64_t)(uint32_t)c.x          << 36)
                 | ((uint64_t)(uint32_t)(n1 + 1024)  << 24)
                 | ((uint64_t)(uint32_t)(n2 + 1024)  << 12)
                 |  (uint64_t)(uint32_t)(n3 + 1024);
    g_keys[i] = key;

    // bucket histogram (bits 35..46); g_hist zeroed by scan kernel each call
    atomicAdd(&g_hist[(uint32_t)(key >> 35)], 1u);

    // zero out_coords region (rows beyond num_unique must stay 0)
    reinterpret_cast<float4*>(out + (size_t)3 * n)[i] = make_float4(0.f, 0.f, 0.f, 0.f);
}

// ---------------------------------------------------------------------------
// Generic single-block exclusive scan over 4096 counters.
// outA = exclusive prefix; outB (optional) = copy of prefix (cursors);
// if reset != 0, zero the input after reading (for graph-replay determinism).
// ---------------------------------------------------------------------------
__global__ void __launch_bounds__(1024)
scan4096_kernel(uint32_t* __restrict__ in, uint32_t* __restrict__ outA,
                uint32_t* __restrict__ outB, uint32_t* __restrict__ total,
                int reset)
{
    __shared__ uint32_t part[1024];
    int t = threadIdx.x;
    uint32_t v[4];
    uint32_t sum = 0;
#pragma unroll
    for (int k = 0; k < 4; k++) { v[k] = in[t * 4 + k]; sum += v[k]; }
    part[t] = sum;
    __syncthreads();
#pragma unroll
    for (int d = 1; d < 1024; d <<= 1) {
        uint32_t x = (t >= d) ? part[t - d] : 0u;
        __syncthreads();
        part[t] += x;
        __syncthreads();
    }
    uint32_t excl = part[t] - sum;
#pragma unroll
    for (int k = 0; k < 4; k++) {
        outA[t * 4 + k] = excl;
        if (outB) outB[t * 4 + k] = excl;
        excl += v[k];
        if (reset) in[t * 4 + k] = 0u;
    }
    if (total && t == 1023) *total = excl;
}

// ---------------------------------------------------------------------------
// Kernel 3: distribute (key, idx) into buckets
// ---------------------------------------------------------------------------
__global__ void distribute_kernel(int n)
{
    int i = blockIdx.x * blockDim.x + threadIdx.x;
    if (i >= n) return;
    uint64_t k = g_keys[i];
    uint32_t b = (uint32_t)(k >> 35);
    uint32_t pos = atomicAdd(&g_cursor[b], 1u);
    g_bkeys[pos] = k;
    g_bvals[pos] = (uint32_t)i;
}

// ---------------------------------------------------------------------------
// Kernel 4: per-bucket first-occurrence marking + unique count
// ---------------------------------------------------------------------------
__global__ void __launch_bounds__(RB_THREADS)
uniqcount_kernel(void)
{
    __shared__ uint64_t skeys[CAP];
    __shared__ uint32_t s_uniq;

    int b = blockIdx.x;
    uint32_t start = g_off[b];
    int cnt = (int)(g_off[b + 1] - start);
    if (threadIdx.x == 0) s_uniq = 0;
    if (cnt == 0) { if (threadIdx.x == 0) g_uniq[b] = 0; return; }

    int t = threadIdx.x;
    for (int p = t; p < cnt; p += RB_THREADS) skeys[p] = g_bkeys[start + p];
    __syncthreads();

    uint32_t my_uniq = 0;
    for (int p = t; p < cnt; p += RB_THREADS) {
        uint64_t k = skeys[p];
        bool first = true;
        for (int j = 0; j < p; j++)
            if (skeys[j] == k) { first = false; break; }
        my_uniq += first ? 1u : 0u;
        // pack first flag into bit 63 (keys use bits 0..46)
        g_bkeys[start + p] = k | (first ? FIRSTBIT : 0ull);
    }
    // warp then block reduce
#pragma unroll
    for (int d = 16; d > 0; d >>= 1)
        my_uniq += __shfl_down_sync(0xFFFFFFFFu, my_uniq, d);
    if ((t & 31) == 0) atomicAdd(&s_uniq, my_uniq);
    __syncthreads();
    if (t == 0) g_uniq[b] = s_uniq;
}

// ---------------------------------------------------------------------------
// Kernel 5: per-bucket rank + inverse map + segment means
// ---------------------------------------------------------------------------
__global__ void __launch_bounds__(RB_THREADS)
finalize_kernel(float* __restrict__ out, int n)
{
    __shared__ uint64_t skeys[CAP];   // with first-bit in bit 63
    __shared__ uint32_t svals[CAP];

    int b = blockIdx.x;
    uint32_t start = g_off[b];
    int cnt = (int)(g_off[b + 1] - start);
    if (cnt == 0) return;

    int t = threadIdx.x;
    for (int p = t; p < cnt; p += RB_THREADS) {
        skeys[p] = g_bkeys[start + p];
        svals[p] = g_bvals[start + p];
    }
    __syncthreads();

    uint32_t base = g_ubase[b];
    const int4* ncp = reinterpret_cast<const int4*>(g_newc);

    for (int p = t; p < cnt; p += RB_THREADS) {
        uint64_t kp = skeys[p];
        uint64_t myk = kp & KEYMASK;
        bool first = (kp & FIRSTBIT) != 0ull;

        uint32_t less = 0;
        float sx = 0.f, sy = 0.f, sz = 0.f, sw = 0.f;
        int ecnt = 0;
        for (int j = 0; j < cnt; j++) {
            uint64_t kj = skeys[j];
            uint64_t kjm = kj & KEYMASK;
            less += (uint32_t)((kjm < myk) & (kj >> 63));
            if (first && kjm == myk) {        // rare beyond j==p
                int4 m = ncp[svals[j]];
                sx += (float)m.x; sy += (float)m.y;
                sz += (float)m.z; sw += (float)m.w;
                ecnt++;
            }
        }
        uint32_t r = base + less;

        // inv map (float32) at offset 7n
        out[(size_t)7 * n + svals[p]] = (float)r;

        if (first) {
            float c = (float)ecnt;
            float* oc = out + (size_t)3 * n + (size_t)4 * r;
            // matches jax: f32 divide then astype(int32) (trunc toward zero)
            oc[0] = (float)(int)(sx / c);
            oc[1] = (float)(int)(sy / c);
            oc[2] = (float)(int)(sz / c);
            oc[3] = (float)(int)(sw / c);
        }
    }
}

// ---------------------------------------------------------------------------
// Host launch
// ---------------------------------------------------------------------------
extern "C" void kernel_launch(void* const* d_in, const int* in_sizes, int n_in,
                              void* d_out, int out_size)
{
    const float* feats  = (const float*)d_in[0];
    const int*   coords = (const int*)d_in[1];
    const int*   mask   = (const int*)d_in[2];
    const float* W1 = (const float*)d_in[3];
    const float* b1 = (const float*)d_in[4];
    const float* W2 = (const float*)d_in[5];
    const float* b2 = (const float*)d_in[6];
    const float* W3 = (const float*)d_in[7];
    const float* b3 = (const float*)d_in[8];
    float* out = (float*)d_out;

    int n = in_sizes[0] / 64;
    if (n > NMAX) n = NMAX;

    void *p_hist, *p_off, *p_cursor, *p_uniq, *p_ubase;
    cudaGetSymbolAddress(&p_hist,   g_hist);
    cudaGetSymbolAddress(&p_off,    g_off);
    cudaGetSymbolAddress(&p_cursor, g_cursor);
    cudaGetSymbolAddress(&p_uniq,   g_uniq);
    cudaGetSymbolAddress(&p_ubase,  g_ubase);

    const int BLK = 256;
    int grid = (n + BLK - 1) / BLK;

    // 1) decode + keys + bucket histogram + out_coords zero
    decode_kernel<<<grid, BLK>>>(feats, coords, mask, W1, b1, W2, b2, W3, b3, out, n);

    // 2) bucket offsets + cursors (and hist reset for replay determinism)
    scan4096_kernel<<<1, 1024>>>((uint32_t*)p_hist, (uint32_t*)p_off,
                                 (uint32_t*)p_cursor,
                                 (uint32_t*)p_off + NBUCKETS, 1);

    // 3) distribute into buckets
    distribute_kernel<<<grid, BLK>>>(n);

    // 4) per-bucket first-occurrence flags + unique counts
    uniqcount_kernel<<<NBUCKETS, RB_THREADS>>>();

    // 5) exclusive scan of unique counts -> global rank bases
    scan4096_kernel<<<1, 1024>>>((uint32_t*)p_uniq, (uint32_t*)p_ubase,
                                 nullptr, nullptr, 0);

    // 6) ranks + inverse map + segment means
    finalize_kernel<<<NBUCKETS, RB_THREADS>>>(out, n);
}